// round 4
// baseline (speedup 1.0000x reference)
#include <cuda_runtime.h>
#include <cuda_fp16.h>

// APPNP: h_{k+1} = (1-a) * Dinv(A+I)Dinv * h_k + a * x,  K=5, a=0.8
// g = dinv .* h stored in FP16, rows padded to 128B (8 x uint4 chunks, 6 used).
// m[v] = dinv[v]*(g[v] + sum_{e:col=v} g[row_e]); accumulation in fp32.
// CSR via atomic segment allocation + rank-from-histogram (atomic-free scatter).

#define NN 100000
#define EE 1600000
#define DD 48
#define CH 6            // used 16B chunks per fp16 row (48 halfs = 96B)
#define CHP 8           // padded chunks per row (128B)
#define ALPHA 0.8f

// ---------------- device scratch (static, no allocation) ----------------
__device__ int   g_ecount[NN];
__device__ float g_dinv[NN];
__device__ int   g_colstart[NN];
__device__ int   g_total;
__device__ int   g_rank[EE];
__device__ int   g_csr_row[EE];
__device__ uint4 g_bufA[NN * CHP];   // fp16 rows, 128B padded
__device__ uint4 g_bufB[NN * CHP];

// ---------------- helpers ----------------
static __device__ __forceinline__ void acc8(float* a, uint4 u) {
    float2 p;
    p = __half22float2(*(__half2*)&u.x); a[0] += p.x; a[1] += p.y;
    p = __half22float2(*(__half2*)&u.y); a[2] += p.x; a[3] += p.y;
    p = __half22float2(*(__half2*)&u.z); a[4] += p.x; a[5] += p.y;
    p = __half22float2(*(__half2*)&u.w); a[6] += p.x; a[7] += p.y;
}

// ---------------- preprocessing ----------------
__global__ void k_zero_counts() {
    int v = blockIdx.x * blockDim.x + threadIdx.x;
    if (v < NN) g_ecount[v] = 0;
    if (v == 0) g_total = 0;
}

// histogram; atomic return value = within-node rank of this edge
__global__ void k_hist(const int* __restrict__ col) {
    int e = blockIdx.x * blockDim.x + threadIdx.x;
    if (e < EE) g_rank[e] = atomicAdd(&g_ecount[col[e]], 1);
}

// claim contiguous segment per node; compute dinv
__global__ void k_alloc() {
    int v = blockIdx.x * blockDim.x + threadIdx.x;
    if (v < NN) {
        int c = g_ecount[v];
        g_colstart[v] = atomicAdd(&g_total, c);
        g_dinv[v]     = rsqrtf((float)(c + 1));   // +1 self loop
    }
}

// atomic-free scatter using precomputed ranks
__global__ void k_scatter(const int* __restrict__ row, const int* __restrict__ col) {
    int e = blockIdx.x * blockDim.x + threadIdx.x;
    if (e < EE) {
        int p = g_colstart[col[e]] + g_rank[e];
        g_csr_row[p] = row[e];
    }
}

// g0 = fp16(dinv .* x), padded rows
__global__ void k_scale_x(const float4* __restrict__ x, uint4* __restrict__ g0) {
    int t = blockIdx.x * blockDim.x + threadIdx.x;   // one 16B fp16 chunk
    if (t >= NN * CH) return;
    int v = t / CH, c = t % CH;
    float s = g_dinv[v];
    float4 a = x[(size_t)v * 12 + 2 * c];
    float4 b = x[(size_t)v * 12 + 2 * c + 1];
    uint4 o;
    *(__half2*)&o.x = __floats2half2_rn(a.x * s, a.y * s);
    *(__half2*)&o.y = __floats2half2_rn(a.z * s, a.w * s);
    *(__half2*)&o.z = __floats2half2_rn(b.x * s, b.y * s);
    *(__half2*)&o.w = __floats2half2_rn(b.z * s, b.w * s);
    g0[(size_t)v * CHP + c] = o;
}

// ---------------- propagation ----------------
// Warp per node. Lane layout: el = lane>>3 (4 edge slots), c = lane&7 (chunk).
// Two edge slots unrolled per loop iter (e, e+4) -> MLP=2 per lane.
// Reduction: shfl_xor 8,16 over 8 floats (16 shfl/node); lane c<6 owns chunk c.
template <bool WRITE_H>
__global__ void __launch_bounds__(256) k_propagate(const uint4* __restrict__ gin,
                                                   const float4* __restrict__ x,
                                                   void* __restrict__ gout_) {
    int v    = (blockIdx.x * blockDim.x + threadIdx.x) >> 5;
    int lane = threadIdx.x & 31;
    if (v >= NN) return;

    int el = lane >> 3;
    int c  = lane & 7;
    bool act = (c < CH);

    int s    = g_colstart[v];
    int eend = s + g_ecount[v];

    float a[8] = {0.f, 0.f, 0.f, 0.f, 0.f, 0.f, 0.f, 0.f};
    float b[8] = {0.f, 0.f, 0.f, 0.f, 0.f, 0.f, 0.f, 0.f};

    for (int base = s; base < eend; base += 8) {
        int e0 = base + el;
        int e1 = base + 4 + el;
        if (e0 < eend && act) {
            int r = g_csr_row[e0];
            uint4 u = __ldg(&gin[(size_t)r * CHP + c]);
            acc8(a, u);
        }
        if (e1 < eend && act) {
            int r = g_csr_row[e1];
            uint4 u = __ldg(&gin[(size_t)r * CHP + c]);
            acc8(b, u);
        }
    }

    #pragma unroll
    for (int j = 0; j < 8; j++) a[j] += b[j];

    // reduce across the 4 edge slots (lane bits 3,4)
    #pragma unroll
    for (int off = 8; off <= 16; off <<= 1) {
        #pragma unroll
        for (int j = 0; j < 8; j++)
            a[j] += __shfl_xor_sync(0xffffffffu, a[j], off);
    }

    if (lane < CH) {   // lane c owns final chunk c (8 dims)
        float di = g_dinv[v];

        uint4 gv = __ldg(&gin[(size_t)v * CHP + lane]);   // self loop
        float gs[8];
        {
            float2 p;
            p = __half22float2(*(__half2*)&gv.x); gs[0] = p.x; gs[1] = p.y;
            p = __half22float2(*(__half2*)&gv.y); gs[2] = p.x; gs[3] = p.y;
            p = __half22float2(*(__half2*)&gv.z); gs[4] = p.x; gs[5] = p.y;
            p = __half22float2(*(__half2*)&gv.w); gs[6] = p.x; gs[7] = p.y;
        }

        float4 xa = __ldg(&x[(size_t)v * 12 + 2 * lane]);
        float4 xb = __ldg(&x[(size_t)v * 12 + 2 * lane + 1]);
        float xs[8] = {xa.x, xa.y, xa.z, xa.w, xb.x, xb.y, xb.z, xb.w};

        float h[8];
        #pragma unroll
        for (int j = 0; j < 8; j++)
            h[j] = (1.0f - ALPHA) * (di * (a[j] + gs[j])) + ALPHA * xs[j];

        if (WRITE_H) {
            float4* out = (float4*)gout_;
            out[(size_t)v * 12 + 2 * lane]     = make_float4(h[0], h[1], h[2], h[3]);
            out[(size_t)v * 12 + 2 * lane + 1] = make_float4(h[4], h[5], h[6], h[7]);
        } else {
            uint4 o;   // store g = dinv * h as fp16
            *(__half2*)&o.x = __floats2half2_rn(h[0] * di, h[1] * di);
            *(__half2*)&o.y = __floats2half2_rn(h[2] * di, h[3] * di);
            *(__half2*)&o.z = __floats2half2_rn(h[4] * di, h[5] * di);
            *(__half2*)&o.w = __floats2half2_rn(h[6] * di, h[7] * di);
            ((uint4*)gout_)[(size_t)v * CHP + lane] = o;
        }
    }
}

// ---------------- launch ----------------
extern "C" void kernel_launch(void* const* d_in, const int* in_sizes, int n_in,
                              void* d_out, int out_size) {
    const float4* x  = (const float4*)d_in[0];
    const int*    ei = (const int*)d_in[1];
    const int* row = ei;          // edge_index[0]
    const int* col = ei + EE;     // edge_index[1]

    uint4 *pA, *pB;
    cudaGetSymbolAddress((void**)&pA, g_bufA);
    cudaGetSymbolAddress((void**)&pB, g_bufB);

    k_zero_counts<<<(NN + 255) / 256, 256>>>();
    k_hist<<<(EE + 255) / 256, 256>>>(col);
    k_alloc<<<(NN + 255) / 256, 256>>>();
    k_scatter<<<(EE + 255) / 256, 256>>>(row, col);
    k_scale_x<<<(NN * CH + 255) / 256, 256>>>(x, pA);

    const int PBLK = 256;                       // 8 warps = 8 nodes per block
    const int PGRID = (NN + 7) / 8;             // 12500
    k_propagate<false><<<PGRID, PBLK>>>(pA, x, pB);   // step 1
    k_propagate<false><<<PGRID, PBLK>>>(pB, x, pA);   // step 2
    k_propagate<false><<<PGRID, PBLK>>>(pA, x, pB);   // step 3
    k_propagate<false><<<PGRID, PBLK>>>(pB, x, pA);   // step 4
    k_propagate<true ><<<PGRID, PBLK>>>(pA, x, d_out); // step 5 -> h (fp32)
}

// round 5
// speedup vs baseline: 1.0234x; 1.0234x over previous
#include <cuda_runtime.h>

// APPNP: h_{k+1} = (1-a) * Dinv(A+I)Dinv * h_k + a * x,  K=5, a=0.8
// g = dinv .* h (fp32). m[v] = dinv[v]*(g[v] + sum_{e:col=v} g[row_e]).
// CSR via atomic segment allocation + rank-from-histogram (atomic-free scatter).
// Propagate: warp/node, 16 edges per iteration (MLP=6) to cover L2 latency.

#define NN 100000
#define EE 1600000
#define DD 48
#define DV 12           // float4 chunks per fp32 row
#define ALPHA 0.8f

// ---------------- device scratch (static, no allocation) ----------------
__device__ int    g_ecount[NN];
__device__ float  g_dinv[NN];
__device__ int    g_colstart[NN];
__device__ int    g_total;
__device__ int    g_rank[EE];
__device__ int    g_csr_row[EE];
__device__ float4 g_bufA[NN * DV];
__device__ float4 g_bufB[NN * DV];

static __device__ __forceinline__ float4 f4add(float4 a, float4 b) {
    return make_float4(a.x + b.x, a.y + b.y, a.z + b.z, a.w + b.w);
}

// ---------------- preprocessing ----------------
__global__ void k_zero_counts() {
    int v = blockIdx.x * blockDim.x + threadIdx.x;
    if (v < NN) g_ecount[v] = 0;
    if (v == 0) g_total = 0;
}

// histogram; atomic return value = within-node rank of this edge
__global__ void k_hist(const int* __restrict__ col) {
    int e = blockIdx.x * blockDim.x + threadIdx.x;
    if (e < EE) g_rank[e] = atomicAdd(&g_ecount[col[e]], 1);
}

// claim contiguous segment per node; compute dinv
__global__ void k_alloc() {
    int v = blockIdx.x * blockDim.x + threadIdx.x;
    if (v < NN) {
        int c = g_ecount[v];
        g_colstart[v] = atomicAdd(&g_total, c);
        g_dinv[v]     = rsqrtf((float)(c + 1));   // +1 self loop
    }
}

// atomic-free scatter using precomputed ranks
__global__ void k_scatter(const int* __restrict__ row, const int* __restrict__ col) {
    int e = blockIdx.x * blockDim.x + threadIdx.x;
    if (e < EE) {
        int p = g_colstart[col[e]] + g_rank[e];
        g_csr_row[p] = row[e];
    }
}

// g0 = dinv .* x
__global__ void k_scale_x(const float4* __restrict__ x, float4* __restrict__ g0) {
    int t = blockIdx.x * blockDim.x + threadIdx.x;
    if (t < NN * DV) {
        int v = t / DV;
        float s = g_dinv[v];
        float4 a = x[t];
        g0[t] = make_float4(a.x * s, a.y * s, a.z * s, a.w * s);
    }
}

// ---------------- propagation ----------------
// Warp per node. el = lane>>2 (8 edge slots), q = lane&3.
// Main loop: 16 edges/iter -> 2 idx loads + 6 independent LDG.128 per lane.
template <bool WRITE_H>
__global__ void __launch_bounds__(256) k_propagate(const float4* __restrict__ gin,
                                                   const float4* __restrict__ x,
                                                   float4* __restrict__ gout) {
    int v    = (blockIdx.x * blockDim.x + threadIdx.x) >> 5;
    int lane = threadIdx.x & 31;
    if (v >= NN) return;

    int el = lane >> 2;
    int q  = lane & 3;

    int s    = g_colstart[v];
    int eend = s + g_ecount[v];

    float4 a0 = make_float4(0.f, 0.f, 0.f, 0.f);
    float4 a1 = a0, a2 = a0;
    float4 b0 = a0, b1 = a0, b2 = a0;

    int b = s;
    // main loop: 16 edges per iteration, no bounds checks inside
    for (; b + 16 <= eend; b += 16) {
        int r0 = __ldg(&g_csr_row[b + el]);
        int r1 = __ldg(&g_csr_row[b + 8 + el]);
        const float4* p0 = gin + (size_t)r0 * DV;
        const float4* p1 = gin + (size_t)r1 * DV;
        float4 u0 = __ldg(&p0[q]);
        float4 u1 = __ldg(&p0[q + 4]);
        float4 u2 = __ldg(&p0[q + 8]);
        float4 w0 = __ldg(&p1[q]);
        float4 w1 = __ldg(&p1[q + 4]);
        float4 w2 = __ldg(&p1[q + 8]);
        a0 = f4add(a0, u0);  a1 = f4add(a1, u1);  a2 = f4add(a2, u2);
        b0 = f4add(b0, w0);  b1 = f4add(b1, w1);  b2 = f4add(b2, w2);
    }
    // tail: 8 edges per iteration, guarded
    for (; b < eend; b += 8) {
        int e = b + el;
        if (e < eend) {
            int r = __ldg(&g_csr_row[e]);
            const float4* p = gin + (size_t)r * DV;
            a0 = f4add(a0, __ldg(&p[q]));
            a1 = f4add(a1, __ldg(&p[q + 4]));
            a2 = f4add(a2, __ldg(&p[q + 8]));
        }
    }
    a0 = f4add(a0, b0);  a1 = f4add(a1, b1);  a2 = f4add(a2, b2);

    // reduce across the 8 edge slots (lane bits 2..4)
    #pragma unroll
    for (int off = 4; off <= 16; off <<= 1) {
        a0.x += __shfl_xor_sync(0xffffffffu, a0.x, off);
        a0.y += __shfl_xor_sync(0xffffffffu, a0.y, off);
        a0.z += __shfl_xor_sync(0xffffffffu, a0.z, off);
        a0.w += __shfl_xor_sync(0xffffffffu, a0.w, off);
        a1.x += __shfl_xor_sync(0xffffffffu, a1.x, off);
        a1.y += __shfl_xor_sync(0xffffffffu, a1.y, off);
        a1.z += __shfl_xor_sync(0xffffffffu, a1.z, off);
        a1.w += __shfl_xor_sync(0xffffffffu, a1.w, off);
        a2.x += __shfl_xor_sync(0xffffffffu, a2.x, off);
        a2.y += __shfl_xor_sync(0xffffffffu, a2.y, off);
        a2.z += __shfl_xor_sync(0xffffffffu, a2.z, off);
        a2.w += __shfl_xor_sync(0xffffffffu, a2.w, off);
    }

    // lanes 0..11 each own output chunk `lane`
    if (lane < 12) {
        int sel = lane >> 2;
        float4 val = (sel == 0) ? a0 : ((sel == 1) ? a1 : a2);

        float  di = g_dinv[v];
        size_t idx = (size_t)v * DV + lane;
        float4 gv = __ldg(&gin[idx]);        // self loop: + g[v]
        float4 xx = __ldg(&x[idx]);

        float4 h;
        h.x = (1.0f - ALPHA) * (di * (val.x + gv.x)) + ALPHA * xx.x;
        h.y = (1.0f - ALPHA) * (di * (val.y + gv.y)) + ALPHA * xx.y;
        h.z = (1.0f - ALPHA) * (di * (val.z + gv.z)) + ALPHA * xx.z;
        h.w = (1.0f - ALPHA) * (di * (val.w + gv.w)) + ALPHA * xx.w;

        if (!WRITE_H) {                      // store g = dinv * h for next step
            h.x *= di; h.y *= di; h.z *= di; h.w *= di;
        }
        gout[idx] = h;
    }
}

// ---------------- launch ----------------
extern "C" void kernel_launch(void* const* d_in, const int* in_sizes, int n_in,
                              void* d_out, int out_size) {
    const float4* x  = (const float4*)d_in[0];
    const int*    ei = (const int*)d_in[1];
    const int* row = ei;          // edge_index[0]
    const int* col = ei + EE;     // edge_index[1]
    float4* out = (float4*)d_out;

    float4 *pA, *pB;
    cudaGetSymbolAddress((void**)&pA, g_bufA);
    cudaGetSymbolAddress((void**)&pB, g_bufB);

    k_zero_counts<<<(NN + 255) / 256, 256>>>();
    k_hist<<<(EE + 255) / 256, 256>>>(col);
    k_alloc<<<(NN + 255) / 256, 256>>>();
    k_scatter<<<(EE + 255) / 256, 256>>>(row, col);
    k_scale_x<<<(NN * DV + 255) / 256, 256>>>(x, pA);

    const int PBLK = 256;                       // 8 warps = 8 nodes per block
    const int PGRID = (NN + 7) / 8;             // 12500
    k_propagate<false><<<PGRID, PBLK>>>(pA, x, pB);   // step 1
    k_propagate<false><<<PGRID, PBLK>>>(pB, x, pA);   // step 2
    k_propagate<false><<<PGRID, PBLK>>>(pA, x, pB);   // step 3
    k_propagate<false><<<PGRID, PBLK>>>(pB, x, pA);   // step 4
    k_propagate<true ><<<PGRID, PBLK>>>(pA, x, out);  // step 5 -> h
}